// round 17
// baseline (speedup 1.0000x reference)
#include <cuda_runtime.h>
#include <cuda_bf16.h>
#include <cuda_fp16.h>
#include <cstdint>
#include <math.h>

#define NB 2
#define CH 512
#define NN1 1024
#define NN2 2048
#define MM1 (NB*NN1)   // 2048 columns
#define MM2 (NB*NN2)   // 4096 columns

// ---------------- device scratch (no allocations allowed) ----------------
__device__ float g_c1[NB*CH];
__device__ float g_cg[NB*CH];
__device__ float g_glob[NB*CH];
__device__ float g_globp[NB*16*CH];
__device__ float g_wx[CH];
__device__ float g_wy[CH];
__device__ int   g_nbr[MM2*64];
__device__ int   g_cnt[MM2];

__device__ __align__(256) __half g_aF[MM2*CH];
__device__ __align__(256) __half g_bF[MM2*CH];
__device__ __align__(256) __half g_cF[MM1*CH];   // n1-branch buffers
__device__ __align__(256) __half g_dF[MM1*CH];
__device__ __align__(256) __half g_featF[MM2*1024];

__device__ __align__(256) __half g_w1bF[CH*CH];
__device__ __align__(256) __half g_w1cF[CH*CH];
__device__ __align__(256) __half g_w2aF[CH*1024];
__device__ __align__(256) __half g_w2bF[CH*CH];
__device__ __align__(256) __half g_w2cF[CH*CH];

#define NEGINF __int_as_float(0xff800000)

// ---------------- host-side streams/events (created at load, before capture) ----
struct HxStreams {
    cudaStream_t s2, s3;
    cudaEvent_t e0, ePrep, eH1n2, eFeat, eCg, eN1;
    HxStreams() {
        cudaStreamCreateWithFlags(&s2, cudaStreamNonBlocking);
        cudaStreamCreateWithFlags(&s3, cudaStreamNonBlocking);
        cudaEventCreateWithFlags(&e0,    cudaEventDisableTiming);
        cudaEventCreateWithFlags(&ePrep, cudaEventDisableTiming);
        cudaEventCreateWithFlags(&eH1n2, cudaEventDisableTiming);
        cudaEventCreateWithFlags(&eFeat, cudaEventDisableTiming);
        cudaEventCreateWithFlags(&eCg,   cudaEventDisableTiming);
        cudaEventCreateWithFlags(&eN1,   cudaEventDisableTiming);
    }
};
static HxStreams g_hx;

// ---------------- PTX helpers (all base-PTX, sm_80-era: safe on compute_103) ----
__device__ __forceinline__ uint32_t smem_u32(const void* p) {
    uint32_t a;
    asm("{ .reg .u64 t; cvta.to.shared.u64 t, %1; cvt.u32.u64 %0, t; }" : "=r"(a) : "l"(p));
    return a;
}
__device__ __forceinline__ void cp16(uint32_t saddr, const void* g) {
    asm volatile("cp.async.cg.shared.global [%0], [%1], 16;" :: "r"(saddr), "l"(g));
}
#define CP_COMMIT() asm volatile("cp.async.commit_group;" ::: "memory")
#define CP_WAIT(n)  asm volatile("cp.async.wait_group %0;" :: "n"(n) : "memory")

__device__ __forceinline__ void ldsm4(uint32_t* r, uint32_t addr) {
    asm volatile("ldmatrix.sync.aligned.m8n8.x4.shared.b16 {%0,%1,%2,%3}, [%4];"
                 : "=r"(r[0]), "=r"(r[1]), "=r"(r[2]), "=r"(r[3]) : "r"(addr));
}
__device__ __forceinline__ void mma16816h(float* c, const uint32_t* a, const uint32_t* b) {
    asm volatile("mma.sync.aligned.m16n8k16.row.col.f32.f16.f16.f32 "
                 "{%0,%1,%2,%3},{%4,%5,%6,%7},{%8,%9},{%0,%1,%2,%3};"
                 : "+f"(c[0]), "+f"(c[1]), "+f"(c[2]), "+f"(c[3])
                 : "r"(a[0]), "r"(a[1]), "r"(a[2]), "r"(a[3]), "r"(b[0]), "r"(b[1]));
}

__device__ __forceinline__ void h_store4(__half* dst, float4 v) {
    __half2* p = (__half2*)dst;
    p[0] = __floats2half2_rn(v.x, v.y);
    p[1] = __floats2half2_rn(v.z, v.w);
}

// ---------------- fused weight preprocessing (all fp16) ----------------
__global__ void k_prep(const float* __restrict__ W1b, const float* __restrict__ W1c,
                       const float* __restrict__ W2b, const float* __restrict__ W2c,
                       const float* __restrict__ W2a) {
    int id = blockIdx.x * 256 + threadIdx.x;
    if (id < 262144) {
        const float* src; __half* dst;
        int seg = id >> 16, off = (id & 65535) * 4;
        if (seg == 0)      { src = W1b; dst = g_w1bF; }
        else if (seg == 1) { src = W1c; dst = g_w1cF; }
        else if (seg == 2) { src = W2b; dst = g_w2bF; }
        else               { src = W2c; dst = g_w2cF; }
        float4 v = *(const float4*)(src + off);
        h_store4(dst + off, v);
    } else if (id < 393216) {
        int e = (id - 262144) * 4;
        int r = e >> 10, c = e & 1023;
        float4 v = *(const float4*)(W2a + r * 1536 + c);
        h_store4(g_w2aF + e, v);
    }
}

__global__ void k_wxy(const float* __restrict__ W1a) {
    int o = blockIdx.x * 256 + threadIdx.x;
    if (o < CH) { g_wx[o] = W1a[o*514 + 512]; g_wy[o] = W1a[o*514 + 513]; }
}

// ---------------- small kernels ----------------
__global__ void k_dotbias(const float* __restrict__ W, int ldw, int off,
                          const float* __restrict__ vec, const float* __restrict__ bias,
                          float* __restrict__ outv) {
    int w = blockIdx.x * 8 + (threadIdx.x >> 5);
    int lane = threadIdx.x & 31;
    int b = w >> 9, o = w & 511;
    const float* wr = W + o * ldw + off;
    const float* vr = vec + b * CH;
    float acc = 0.f;
    for (int c = lane; c < CH; c += 32) acc = fmaf(wr[c], vr[c], acc);
    #pragma unroll
    for (int s = 16; s; s >>= 1) acc += __shfl_xor_sync(0xffffffffu, acc, s);
    if (lane == 0) outv[w] = acc + bias[o];
}

template <int N_, int SIDE>
__global__ void k_h1(__half* __restrict__ dst) {
    int id = blockIdx.x * 256 + threadIdx.x;
    int col = id >> 7, o = (id & 127) * 4;
    int b = (col >= N_) ? 1 : 0;
    int i = col - b * N_;
    int ix = i / SIDE, iy = i - ix * SIDE;
    const float inv = 1.f / (float)(SIDE - 1);
    float lx = (float)ix * inv, ly = (float)iy * inv;
    float4 c4 = *(const float4*)&g_c1[b*CH + o];
    float4 wx = *(const float4*)&g_wx[o];
    float4 wy = *(const float4*)&g_wy[o];
    float4 v;
    v.x = c4.x + wx.x * lx + wy.x * ly;
    v.y = c4.y + wx.y * lx + wy.y * ly;
    v.z = c4.z + wx.z * lx + wy.z * ly;
    v.w = c4.w + wx.w * lx + wy.w * ly;
    v.x = v.x > 0.f ? v.x : 0.2f * v.x;
    v.y = v.y > 0.f ? v.y : 0.2f * v.y;
    v.z = v.z > 0.f ? v.z : 0.2f * v.z;
    v.w = v.w > 0.f ? v.w : 0.2f * v.w;
    h_store4(dst + (size_t)col * CH + o, v);
}

// ---------------- fp16 HMMA GEMM: Y = lrelu(bias + X @ W^T) ----------------
#define TH_STAGE 24576
#define TH_SMEM  (2*TH_STAGE)

__device__ __forceinline__ uint32_t sw_off(int row, int chunk) {
    return (uint32_t)(row * 128 + ((chunk ^ (row & 7)) * 16));
}

__device__ __forceinline__ void th_issue(int t, uint32_t s0,
    const __half* __restrict__ Xf, int ldx, int mBase,
    const __half* __restrict__ Wf, int ldw, int nBase, int k0) {
    #pragma unroll
    for (int j = 0; j < 4; j++) {               // A
        int id = t + 256 * j;
        int r = id >> 3, c = id & 7;
        cp16(s0 + sw_off(r, c), Xf + (size_t)(mBase + r) * ldx + k0 + c * 8);
    }
    #pragma unroll
    for (int j = 0; j < 2; j++) {               // B
        int id = t + 256 * j;
        int r = id >> 3, c = id & 7;
        cp16(s0 + 16384 + sw_off(r, c), Wf + (size_t)(nBase + r) * ldw + k0 + c * 8);
    }
    CP_COMMIT();
}

__global__ __launch_bounds__(256, 2)
void k_hgemm(const __half* __restrict__ Xf, int ldx,
             const __half* __restrict__ Wf, int ldw,
             const float* __restrict__ bias, int biasB,
             __half* __restrict__ Yf, int ldy, int K, int nPerB) {
    extern __shared__ char sm[];
    uint32_t sbase = smem_u32(sm);
    int t = threadIdx.x, lane = t & 31, w = t >> 5;
    int wm = w & 3, wn = w >> 2;
    int mBase = blockIdx.x * 128, nBase = blockIdx.y * 64;

    float acc[2][4][4];
    #pragma unroll
    for (int mi = 0; mi < 2; mi++)
        #pragma unroll
        for (int nj = 0; nj < 4; nj++)
            #pragma unroll
            for (int q = 0; q < 4; q++) acc[mi][nj][q] = 0.f;

    int rowA0 = wm * 32 + (lane & 15);
    int khA   = lane >> 4;
    int rowB0 = wn * 32 + ((lane >> 4) & 1) * 8 + (lane & 7);
    int khB   = (lane >> 3) & 1;

    int nIter = K >> 6;
    th_issue(t, sbase, Xf, ldx, mBase, Wf, ldw, nBase, 0);

    for (int it = 0; it < nIter; it++) {
        if (it + 1 < nIter) {
            th_issue(t, sbase + ((it + 1) & 1) * TH_STAGE,
                     Xf, ldx, mBase, Wf, ldw, nBase, (it + 1) << 6);
            CP_WAIT(1);
        } else {
            CP_WAIT(0);
        }
        __syncthreads();

        uint32_t sA = sbase + (it & 1) * TH_STAGE;
        uint32_t sB = sA + 16384;
        #pragma unroll
        for (int kt = 0; kt < 4; kt++) {
            uint32_t Af[2][4];
            uint32_t Bf[2][4];
            #pragma unroll
            for (int mi = 0; mi < 2; mi++)
                ldsm4(Af[mi], sA + sw_off(rowA0 + mi * 16, kt * 2 + khA));
            #pragma unroll
            for (int pr = 0; pr < 2; pr++)
                ldsm4(Bf[pr], sB + sw_off(rowB0 + pr * 16, kt * 2 + khB));
            #pragma unroll
            for (int mi = 0; mi < 2; mi++)
                #pragma unroll
                for (int nj = 0; nj < 4; nj++)
                    mma16816h(acc[mi][nj], Af[mi], &Bf[nj >> 1][(nj & 1) * 2]);
        }
        __syncthreads();
    }

    int g = lane >> 2, tq = lane & 3;
    #pragma unroll
    for (int mi = 0; mi < 2; mi++) {
        #pragma unroll
        for (int h = 0; h < 2; h++) {
            int m = mBase + wm * 32 + mi * 16 + g + h * 8;
            const float* bp = bias + ((m >= nPerB) ? biasB : 0);
            size_t ro = (size_t)m * ldy;
            #pragma unroll
            for (int nj = 0; nj < 4; nj++) {
                int n = nBase + wn * 32 + nj * 8 + 2 * tq;
                float v0 = acc[mi][nj][h * 2 + 0] + bp[n];
                float v1 = acc[mi][nj][h * 2 + 1] + bp[n + 1];
                v0 = v0 > 0.f ? v0 : 0.2f * v0;
                v1 = v1 > 0.f ? v1 : 0.2f * v1;
                *(__half2*)(Yf + ro + n) = __floats2half2_rn(v0, v1);
            }
        }
    }
}

// ---------------- sigmoid head (fp16 input) ----------------
__global__ void k_headF(const __half* __restrict__ Xf, int ldx,
                        const float* __restrict__ Wx, const float* __restrict__ bx,
                        float* __restrict__ outp, const float* __restrict__ fine, int M) {
    int w = blockIdx.x * 8 + (threadIdx.x >> 5);
    int lane = threadIdx.x & 31;
    if (w >= M) return;
    const __half* xr = Xf + (size_t)w * ldx;
    float a0 = 0.f, a1 = 0.f, a2 = 0.f;
    for (int c = lane * 2; c < CH; c += 64) {
        __half2 h2 = *(const __half2*)(xr + c);
        float va = __half2float(h2.x), vb = __half2float(h2.y);
        a0 = fmaf(Wx[c], va, fmaf(Wx[c+1], vb, a0));
        a1 = fmaf(Wx[CH + c], va, fmaf(Wx[CH + c + 1], vb, a1));
        a2 = fmaf(Wx[2*CH + c], va, fmaf(Wx[2*CH + c + 1], vb, a2));
    }
    #pragma unroll
    for (int s = 16; s; s >>= 1) {
        a0 += __shfl_xor_sync(0xffffffffu, a0, s);
        a1 += __shfl_xor_sync(0xffffffffu, a1, s);
        a2 += __shfl_xor_sync(0xffffffffu, a2, s);
    }
    if (lane < 3) {
        float a = (lane == 0) ? a0 : ((lane == 1) ? a1 : a2);
        float sv = 1.f / (1.f + expf(-(a + bx[lane]))) - 0.5f;
        if (fine) sv = fine[w*3 + lane] + 0.1f * sv;
        outp[w*3 + lane] = sv;
    }
}

// ---------------- ball query ----------------
__global__ void k_ballq(const float* __restrict__ P) {
    __shared__ float sp[NN2 * 3];
    int w = blockIdx.x * 8 + (threadIdx.x >> 5);
    int lane = threadIdx.x & 31;
    int b = w >> 11, i = w & 2047;
    for (int q = threadIdx.x; q < NN2 * 3; q += 256) sp[q] = P[b * NN2 * 3 + q];
    __syncthreads();
    float pix = sp[i*3], piy = sp[i*3+1], piz = sp[i*3+2];
    float sqi = pix*pix + piy*piy + piz*piz;
    int cnt = 0, firstj = 0;
    bool haveFirst = false;
    int base = w * 64;
    for (int jb = 0; jb < NN2; jb += 32) {
        int j = jb + lane;
        float x = sp[j*3], y = sp[j*3+1], zz = sp[j*3+2];
        float d2 = sqi + (x*x + y*y + zz*zz) - 2.f * (pix*x + piy*y + piz*zz);
        bool flag = d2 < 0.01f;
        unsigned mask = __ballot_sync(0xffffffffu, flag);
        int pos = cnt + __popc(mask & ((1u << lane) - 1u));
        if (flag && pos < 64) g_nbr[base + pos] = j;
        if (!haveFirst && mask) { firstj = jb + __ffs(mask) - 1; haveFirst = true; }
        cnt += __popc(mask);
        if (cnt >= 64) break;
    }
    if (cnt < 64)
        for (int tt = cnt + lane; tt < 64; tt += 32) g_nbr[base + tt] = firstj;
    if (lane == 0) g_cnt[w] = min(cnt, 64);
}

// ---------------- global feature max (fp16 feats) ----------------
__global__ void k_globp() {
    int b = blockIdx.x, chunk = blockIdx.y, o = threadIdx.x;  // 512 threads
    float m = NEGINF;
    size_t base = (size_t)(b * NN2 + chunk * 128) * 1024 + o;
    for (int i = 0; i < 128; i++)
        m = fmaxf(m, __half2float(g_featF[base + (size_t)i * 1024]));
    g_globp[(b * 16 + chunk) * CH + o] = m;
}
__global__ void k_globr() {
    int idx = blockIdx.x * 256 + threadIdx.x;
    int b = idx >> 9, o = idx & 511;
    float m = NEGINF;
    for (int c = 0; c < 16; c++) m = fmaxf(m, g_globp[(b * 16 + c) * CH + o]);
    g_glob[idx] = m;
}

// ---------------- neighborhood max: union dedup + smem staging (exact) -------
// 8 queries/block, 256 threads. Union U of the 8 lists staged once in smem
// (<=MAXU rows of 1KB); per-query maxes read smem. Fallback: direct L2 gather.
#define LQ    8
#define MAXU  160
#define LOC_ROWS_B   (MAXU*CH*2)                  // 163840
#define LOC_SLOTS_B  (LOC_ROWS_B)                 // int[MAXU]
#define LOC_LUT_B    (LOC_SLOTS_B + MAXU*4)       // uint16[2048]
#define LOC_ILIST_B  (LOC_LUT_B + 4096)           // int[512]
#define LOC_BMP_B    (LOC_ILIST_B + 2048)         // uint32[64]
#define LOC_WCNT_B   (LOC_BMP_B + 256)            // int[64]
#define LOC_SMEM     (LOC_WCNT_B + 256)

__global__ __launch_bounds__(256, 1)
void k_local() {
    extern __shared__ char dsm[];
    __half*   rows  = (__half*)dsm;
    int*      slots = (int*)(dsm + LOC_SLOTS_B);
    uint16_t* lut   = (uint16_t*)(dsm + LOC_LUT_B);
    int*      ilist = (int*)(dsm + LOC_ILIST_B);
    uint32_t* bmp   = (uint32_t*)(dsm + LOC_BMP_B);
    int*      wcnt  = (int*)(dsm + LOC_WCNT_B);
    __shared__ int s_u;
    __shared__ int s_kc[LQ];

    int t = threadIdx.x;
    int col0 = blockIdx.x * LQ;
    int b = col0 >> 11;
    size_t fbase = (size_t)b * NN2 * 1024;

    if (t < 64) bmp[t] = 0;
    if (t < LQ) s_kc[t] = g_cnt[col0 + t];
    __syncthreads();
    #pragma unroll
    for (int e = t; e < LQ * 64; e += 256) {
        int j = g_nbr[col0 * 64 + e];
        ilist[e] = j;
        atomicOr(&bmp[j >> 5], 1u << (j & 31));
    }
    __syncthreads();
    if (t < 64) wcnt[t] = __popc(bmp[t]);
    __syncthreads();
    if (t == 0) {
        int run = 0;
        for (int w = 0; w < 64; w++) { int tmp = wcnt[w]; wcnt[w] = run; run += tmp; }
        s_u = run;
    }
    __syncthreads();
    int U = s_u;

    if (U <= MAXU) {
        if (t < 64) {
            int base = wcnt[t];
            uint32_t bits = bmp[t];
            while (bits) {
                int bt = __ffs(bits) - 1;
                bits &= bits - 1;
                int j = t * 32 + bt;
                lut[j] = (uint16_t)base;
                slots[base] = j;
                base++;
            }
        }
        __syncthreads();
        // stage U rows (uint4 = 8 halves; 64 uint4 per row)
        for (int e = t; e < U * 64; e += 256) {
            int r = e >> 6, c = e & 63;
            ((uint4*)rows)[r * 64 + c] =
                ((const uint4*)(g_featF + fbase + (size_t)slots[r] * 1024))[c];
        }
        __syncthreads();
        int c = t * 2;
        #pragma unroll
        for (int q = 0; q < LQ; q++) {
            const int* il = ilist + q * 64;
            int kc = s_kc[q];
            __half2 m = __floats2half2_rn(-65504.f, -65504.f);
            for (int k = 0; k < kc; k++) {
                int sl = lut[il[k]];
                m = __hmax2(m, *(const __half2*)(rows + sl * CH + c));
            }
            *(__half2*)(g_featF + (size_t)(col0 + q) * 1024 + 512 + c) = m;
        }
    } else {
        int c = t * 2;
        for (int q = 0; q < LQ; q++) {
            const int* il = ilist + q * 64;
            int kc = s_kc[q];
            __half2 m = __floats2half2_rn(-65504.f, -65504.f);
            for (int k = 0; k < kc; k++) {
                int j = il[k];
                m = __hmax2(m, *(const __half2*)(g_featF + fbase + (size_t)j * 1024 + c));
            }
            *(__half2*)(g_featF + (size_t)(col0 + q) * 1024 + 512 + c) = m;
        }
    }
}

// ---------------- launch ----------------
extern "C" void kernel_launch(void* const* d_in, const int* in_sizes, int n_in,
                              void* d_out, int out_size) {
    const float* z   = (const float*)d_in[0];
    const float* W1a = (const float*)d_in[1];
    const float* b1a = (const float*)d_in[2];
    const float* W1b = (const float*)d_in[3];
    const float* b1b = (const float*)d_in[4];
    const float* W1c = (const float*)d_in[5];
    const float* b1c = (const float*)d_in[6];
    const float* Wx1 = (const float*)d_in[7];
    const float* bx1 = (const float*)d_in[8];
    const float* W2a = (const float*)d_in[9];
    const float* b2a = (const float*)d_in[10];
    const float* W2b = (const float*)d_in[11];
    const float* b2b = (const float*)d_in[12];
    const float* W2c = (const float*)d_in[13];
    const float* b2c = (const float*)d_in[14];
    const float* Wx2 = (const float*)d_in[15];
    const float* bx2 = (const float*)d_in[16];

    float* out  = (float*)d_out;
    float* out1 = out;
    float* out2 = out + MM1 * 3;
    float* outF = out + MM1 * 3 + MM2 * 3;

    float* c1p; cudaGetSymbolAddress((void**)&c1p, g_c1);
    float* cgp; cudaGetSymbolAddress((void**)&cgp, g_cg);
    float* glp; cudaGetSymbolAddress((void**)&glp, g_glob);
    __half *aF, *bF, *cF, *dF, *fF;
    cudaGetSymbolAddress((void**)&aF, g_aF); cudaGetSymbolAddress((void**)&bF, g_bF);
    cudaGetSymbolAddress((void**)&cF, g_cF); cudaGetSymbolAddress((void**)&dF, g_dF);
    cudaGetSymbolAddress((void**)&fF, g_featF);
    __half *w1bF, *w1cF, *w2aF, *w2bF, *w2cF;
    cudaGetSymbolAddress((void**)&w1bF, g_w1bF); cudaGetSymbolAddress((void**)&w1cF, g_w1cF);
    cudaGetSymbolAddress((void**)&w2aF, g_w2aF);
    cudaGetSymbolAddress((void**)&w2bF, g_w2bF); cudaGetSymbolAddress((void**)&w2cF, g_w2cF);

    cudaFuncSetAttribute(k_hgemm, cudaFuncAttributeMaxDynamicSharedMemorySize, TH_SMEM);
    cudaFuncSetAttribute(k_local, cudaFuncAttributeMaxDynamicSharedMemorySize, LOC_SMEM);

    cudaStream_t sd = 0, s2 = g_hx.s2, s3 = g_hx.s3;

    // fork point
    cudaEventRecord(g_hx.e0, sd);
    cudaStreamWaitEvent(s2, g_hx.e0, 0);
    cudaStreamWaitEvent(s3, g_hx.e0, 0);

    // ---- d: weight prep (all fp16 conversions) ----
    k_prep<<<1536, 256, 0, sd>>>(W1b, W1c, W2b, W2c, W2a);
    cudaEventRecord(g_hx.ePrep, sd);

    // ---- s2: wxy + c1 + both h1's ----
    k_wxy<<<2, 256, 0, s2>>>(W1a);
    k_dotbias<<<128, 256, 0, s2>>>(W1a, 514, 0, z, b1a, c1p);
    k_h1<NN2, 46><<<MM2/2, 256, 0, s2>>>(aF);
    cudaEventRecord(g_hx.eH1n2, s2);
    k_h1<NN1, 32><<<MM1/2, 256, 0, s2>>>(cF);

    // ---- d: n2 branch ----
    cudaStreamWaitEvent(sd, g_hx.eH1n2, 0);
    k_hgemm<<<dim3(MM2/128, 8), 256, TH_SMEM, sd>>>(aF, 512, w1bF, 512,
                                                    b1b, 0, bF, 512, 512, NN2);
    k_hgemm<<<dim3(MM2/128, 8), 256, TH_SMEM, sd>>>(bF, 512, w1cF, 512,
                                                    b1c, 0, fF, 1024, 512, NN2);
    cudaEventRecord(g_hx.eFeat, sd);
    k_headF<<<MM2/8, 256, 0, sd>>>(fF, 1024, Wx1, bx1, outF, (const float*)0, MM2);

    // ---- s2: n1 branch fills the head/ballq/local window ----
    cudaStreamWaitEvent(s2, g_hx.ePrep, 0);
    cudaStreamWaitEvent(s2, g_hx.eFeat, 0);
    k_hgemm<<<dim3(MM1/128, 8), 256, TH_SMEM, s2>>>(cF, 512, w1bF, 512,
                                                    b1b, 0, dF, 512, 512, NN1);
    k_hgemm<<<dim3(MM1/128, 8), 256, TH_SMEM, s2>>>(dF, 512, w1cF, 512,
                                                    b1c, 0, cF, 512, 512, NN1);
    k_headF<<<MM1/8, 256, 0, s2>>>(cF, 512, Wx1, bx1, out1, (const float*)0, MM1);
    cudaEventRecord(g_hx.eN1, s2);

    // ---- s3: global-max chain ----
    cudaStreamWaitEvent(s3, g_hx.eFeat, 0);
    k_globp<<<dim3(2, 16), 512, 0, s3>>>();
    k_globr<<<4, 256, 0, s3>>>();
    k_dotbias<<<128, 256, 0, s3>>>(W2a, 1536, 1024, glp, b2a, cgp);
    cudaEventRecord(g_hx.eCg, s3);

    // ---- d: ballq + local ----
    k_ballq<<<512, 256, 0, sd>>>(outF);
    k_local<<<MM2/LQ, 256, LOC_SMEM, sd>>>();

    // ---- d: stage2 MLP (fp16) + delta head ----
    cudaStreamWaitEvent(sd, g_hx.eCg, 0);
    k_hgemm<<<dim3(MM2/128, 8), 256, TH_SMEM, sd>>>(fF, 1024, w2aF, 1024,
                                                    cgp, 512, aF, 512, 1024, NN2);
    k_hgemm<<<dim3(MM2/128, 8), 256, TH_SMEM, sd>>>(aF, 512, w2bF, 512,
                                                    b2b, 0, bF, 512, 512, NN2);
    k_hgemm<<<dim3(MM2/128, 8), 256, TH_SMEM, sd>>>(bF, 512, w2cF, 512,
                                                    b2c, 0, aF, 512, 512, NN2);
    cudaStreamWaitEvent(sd, g_hx.eN1, 0);
    k_headF<<<MM2/8, 256, 0, sd>>>(aF, 512, Wx2, bx2, out2, outF, MM2);
}